// round 1
// baseline (speedup 1.0000x reference)
#include <cuda_runtime.h>

#define N_NODES   100000
#define N_EDGES   1600000
#define FEAT      64
#define N_GRAPHS  256
#define N_CLASSES 45

// Scratch (no allocations allowed): two activation buffers + dinv + pooling.
__device__ float g_h[N_NODES * FEAT];     // post-GEMM features (h = in @ W)
__device__ float g_act[N_NODES * FEAT];   // aggregated layer output
__device__ float g_dinv[N_NODES];         // deg -> deg^{-1/2}
__device__ float g_pool[N_GRAPHS * FEAT];
__device__ float g_cnt[N_GRAPHS];

// ---------------------------------------------------------------- degree
__global__ void k_deg_init() {
    int i = blockIdx.x * blockDim.x + threadIdx.x;
    if (i < N_NODES) g_dinv[i] = 1.0f;   // self-loop
}

__global__ void k_deg_count(const int* __restrict__ dst) {
    int e = blockIdx.x * blockDim.x + threadIdx.x;
    if (e < N_EDGES) atomicAdd(&g_dinv[dst[e]], 1.0f);
}

__global__ void k_dinv() {
    int i = blockIdx.x * blockDim.x + threadIdx.x;
    if (i < N_NODES) g_dinv[i] = rsqrtf(g_dinv[i]);
}

// ---------------------------------------------------------------- GEMM h = in @ W  (64x64 W)
// 64 rows per block, 256 threads, each thread computes 4 rows x 4 cols.
__global__ void k_gemm(const float* __restrict__ in, const float* __restrict__ W,
                       float* __restrict__ out, int relu_in) {
    __shared__ float Ws[64 * 64];
    __shared__ float Xs[64 * 64];
    int tid = threadIdx.x;
    int row0 = blockIdx.x * 64;

#pragma unroll
    for (int i = 0; i < 16; i++) Ws[tid + i * 256] = W[tid + i * 256];

#pragma unroll
    for (int i = 0; i < 16; i++) {
        int lin = tid + i * 256;
        int r = lin >> 6;
        int gr = row0 + r;
        float v = 0.0f;
        if (gr < N_NODES) v = in[gr * 64 + (lin & 63)];
        if (relu_in) v = fmaxf(v, 0.0f);
        Xs[lin] = v;
    }
    __syncthreads();

    int tx = tid & 15;   // col group: cols {tx, tx+16, tx+32, tx+48}
    int ty = tid >> 4;   // row group: rows ty*4 .. ty*4+3
    float acc[4][4] = {};

#pragma unroll
    for (int k = 0; k < 64; k += 4) {
        float4 xv[4];
#pragma unroll
        for (int j = 0; j < 4; j++)
            xv[j] = *(const float4*)&Xs[(ty * 4 + j) * 64 + k];
#pragma unroll
        for (int kk = 0; kk < 4; kk++) {
            float w0 = Ws[(k + kk) * 64 + tx];
            float w1 = Ws[(k + kk) * 64 + tx + 16];
            float w2 = Ws[(k + kk) * 64 + tx + 32];
            float w3 = Ws[(k + kk) * 64 + tx + 48];
#pragma unroll
            for (int j = 0; j < 4; j++) {
                float x = (&xv[j].x)[kk];
                acc[j][0] += x * w0;
                acc[j][1] += x * w1;
                acc[j][2] += x * w2;
                acc[j][3] += x * w3;
            }
        }
    }

#pragma unroll
    for (int j = 0; j < 4; j++) {
        int gr = row0 + ty * 4 + j;
        if (gr < N_NODES) {
            out[gr * 64 + tx]      = acc[j][0];
            out[gr * 64 + tx + 16] = acc[j][1];
            out[gr * 64 + tx + 32] = acc[j][2];
            out[gr * 64 + tx + 48] = acc[j][3];
        }
    }
}

// ---------------------------------------------------------------- agg = h * dinv^2 + b
__global__ void k_selfloop(const float* __restrict__ h, const float* __restrict__ b,
                           float* __restrict__ agg) {
    int idx = blockIdx.x * blockDim.x + threadIdx.x;  // over N*16 float4s
    if (idx >= N_NODES * 16) return;
    int n = idx >> 4;
    int q = idx & 15;
    float d = g_dinv[n];
    float dd = d * d;
    float4 hv = *(const float4*)(h + idx * 4);
    float4 bv = *(const float4*)(b + q * 4);
    float4 o;
    o.x = hv.x * dd + bv.x;
    o.y = hv.y * dd + bv.y;
    o.z = hv.z * dd + bv.z;
    o.w = hv.w * dd + bv.w;
    *(float4*)(agg + idx * 4) = o;
}

// ---------------------------------------------------------------- edge scatter: agg[dst] += h[src]*coef
// 16 threads per edge, each handles one float4 and issues one vector red.
__global__ void k_scatter(const float* __restrict__ h, float* __restrict__ agg,
                          const int* __restrict__ src, const int* __restrict__ dst) {
    int t = blockIdx.x * blockDim.x + threadIdx.x;
    int e = t >> 4;
    if (e >= N_EDGES) return;
    int q = t & 15;
    int s = src[e];
    int d = dst[e];
    float c = g_dinv[s] * g_dinv[d];
    float4 v = *(const float4*)(h + s * 64 + q * 4);
    float* p = agg + d * 64 + q * 4;
    asm volatile("red.global.add.v4.f32 [%0], {%1, %2, %3, %4};"
                 :: "l"(p), "f"(v.x * c), "f"(v.y * c), "f"(v.z * c), "f"(v.w * c)
                 : "memory");
}

// ---------------------------------------------------------------- pooling
__global__ void k_pool_zero() {
    int i = blockIdx.x * blockDim.x + threadIdx.x;
    if (i < N_GRAPHS * FEAT) g_pool[i] = 0.0f;
    if (i < N_GRAPHS) g_cnt[i] = 0.0f;
}

#define POOL_NODES 256
__global__ void k_pool(const float* __restrict__ hin, const int* __restrict__ batch) {
    int f = threadIdx.x;                 // 64 threads, one per feature
    int n0 = blockIdx.x * POOL_NODES;
    if (n0 >= N_NODES) return;
    int n1 = n0 + POOL_NODES;
    if (n1 > N_NODES) n1 = N_NODES;

    float acc = 0.0f;
    float cnt = 0.0f;
    int curg = batch[n0];
    for (int n = n0; n < n1; n++) {
        int g = batch[n];
        if (g != curg) {
            atomicAdd(&g_pool[curg * 64 + f], acc);
            if (f == 0) atomicAdd(&g_cnt[curg], cnt);
            acc = 0.0f;
            cnt = 0.0f;
            curg = g;
        }
        acc += hin[n * 64 + f];
        cnt += 1.0f;
    }
    atomicAdd(&g_pool[curg * 64 + f], acc);
    if (f == 0) atomicAdd(&g_cnt[curg], cnt);
}

// ---------------------------------------------------------------- head: out = (pool/cnt) @ Wl + bl
__global__ void k_final(const float* __restrict__ Wl, const float* __restrict__ bl,
                        float* __restrict__ out) {
    int g = blockIdx.x;
    int tid = threadIdx.x;  // 64
    __shared__ float p[64];
    float inv = 1.0f / fmaxf(g_cnt[g], 1.0f);
    p[tid] = g_pool[g * 64 + tid] * inv;
    __syncthreads();
    if (tid < N_CLASSES) {
        float acc = bl[tid];
#pragma unroll
        for (int k = 0; k < 64; k++) acc += p[k] * Wl[k * N_CLASSES + tid];
        out[g * N_CLASSES + tid] = acc;
    }
}

// ---------------------------------------------------------------- launch
extern "C" void kernel_launch(void* const* d_in, const int* in_sizes, int n_in,
                              void* d_out, int out_size) {
    const float* x     = (const float*)d_in[0];
    const int*   ei    = (const int*)d_in[1];
    const int*   batch = (const int*)d_in[2];
    const float* W1    = (const float*)d_in[3];
    const float* b1    = (const float*)d_in[4];
    const float* W2    = (const float*)d_in[5];
    const float* b2    = (const float*)d_in[6];
    const float* W3    = (const float*)d_in[7];
    const float* b3    = (const float*)d_in[8];
    const float* Wl    = (const float*)d_in[9];
    const float* bl    = (const float*)d_in[10];
    const int* src = ei;
    const int* dst = ei + N_EDGES;

    float *h, *act;
    cudaGetSymbolAddress((void**)&h, g_h);
    cudaGetSymbolAddress((void**)&act, g_act);

    const int TPB = 256;
    int grid_n     = (N_NODES + TPB - 1) / TPB;
    int grid_e     = (N_EDGES + TPB - 1) / TPB;
    int grid_gemm  = (N_NODES + 63) / 64;
    int grid_self  = (N_NODES * 16 + TPB - 1) / TPB;
    int grid_scat  = (N_EDGES * 16) / TPB;          // divides exactly
    int grid_pool  = (N_NODES + POOL_NODES - 1) / POOL_NODES;

    // dinv (shared across layers)
    k_deg_init<<<grid_n, TPB>>>();
    k_deg_count<<<grid_e, TPB>>>(dst);
    k_dinv<<<grid_n, TPB>>>();

    // layer 1
    k_gemm<<<grid_gemm, TPB>>>(x, W1, h, 0);
    k_selfloop<<<grid_self, TPB>>>(h, b1, act);
    k_scatter<<<grid_scat, TPB>>>(h, act, src, dst);

    // layer 2 (relu fused into gemm input read)
    k_gemm<<<grid_gemm, TPB>>>(act, W2, h, 1);
    k_selfloop<<<grid_self, TPB>>>(h, b2, act);
    k_scatter<<<grid_scat, TPB>>>(h, act, src, dst);

    // layer 3
    k_gemm<<<grid_gemm, TPB>>>(act, W3, h, 1);
    k_selfloop<<<grid_self, TPB>>>(h, b3, act);
    k_scatter<<<grid_scat, TPB>>>(h, act, src, dst);

    // mean pool + head
    k_pool_zero<<<(N_GRAPHS * FEAT + TPB - 1) / TPB, TPB>>>();
    k_pool<<<grid_pool, 64>>>(act, batch);
    k_final<<<N_GRAPHS, 64>>>(Wl, bl, (float*)d_out);
}

// round 2
// speedup vs baseline: 1.1509x; 1.1509x over previous
#include <cuda_runtime.h>

#define N_NODES   100000
#define N_EDGES   1600000
#define FEAT      64
#define N_GRAPHS  256
#define N_CLASSES 45

#define SCAN_BLK  1024
#define SCAN_NBLK ((N_NODES + SCAN_BLK - 1) / SCAN_BLK)   // 98

// ---- scratch (static; no allocations allowed) ----
__device__ float g_h[N_NODES * FEAT];      // post-GEMM features
__device__ float g_act[N_NODES * FEAT];    // aggregated layer output
__device__ float g_dinv[N_NODES];          // deg^{-1/2}
__device__ int   g_deg[N_NODES];           // in-degree histogram
__device__ int   g_scan[N_NODES];          // per-block inclusive scan
__device__ int   g_bsum[SCAN_NBLK];        // block sums -> exclusive scanned
__device__ int   g_off[N_NODES + 1];       // CSR row offsets
__device__ int   g_cursor[N_NODES];        // fill cursors
__device__ int   g_esrc[N_EDGES];          // CSR: src node per slot
__device__ float g_ecoef[N_EDGES];         // CSR: dinv[src]*dinv[dst] per slot
__device__ float g_pool[N_GRAPHS * FEAT];
__device__ float g_cnt[N_GRAPHS];

// ================================================================ CSR build
__global__ void k_zero_deg() {
    int i = blockIdx.x * blockDim.x + threadIdx.x;
    if (i < N_NODES) g_deg[i] = 0;
}

__global__ void k_hist(const int* __restrict__ dst) {
    int e = blockIdx.x * blockDim.x + threadIdx.x;
    if (e < N_EDGES) atomicAdd(&g_deg[dst[e]], 1);
}

// block-local inclusive scan (Hillis-Steele) + block totals
__global__ void k_scanA() {
    __shared__ int s[SCAN_BLK];
    int t = threadIdx.x;
    int idx = blockIdx.x * SCAN_BLK + t;
    int v = (idx < N_NODES) ? g_deg[idx] : 0;
    s[t] = v;
    __syncthreads();
#pragma unroll
    for (int off = 1; off < SCAN_BLK; off <<= 1) {
        int x = (t >= off) ? s[t - off] : 0;
        __syncthreads();
        s[t] += x;
        __syncthreads();
    }
    if (idx < N_NODES) g_scan[idx] = s[t];
    if (t == SCAN_BLK - 1) g_bsum[blockIdx.x] = s[t];
}

// serial exclusive scan of block sums (tiny: 98 values)
__global__ void k_scanB() {
    if (threadIdx.x == 0) {
        int run = 0;
        for (int i = 0; i < SCAN_NBLK; i++) {
            int v = g_bsum[i];
            g_bsum[i] = run;
            run += v;
        }
    }
}

// finalize offsets (exclusive), dinv, reset cursors
__global__ void k_scanC() {
    int idx = blockIdx.x * blockDim.x + threadIdx.x;
    if (idx < N_NODES) {
        int deg = g_deg[idx];
        int incl = g_scan[idx] + g_bsum[idx / SCAN_BLK];
        g_off[idx] = incl - deg;            // exclusive offset
        g_dinv[idx] = rsqrtf((float)deg + 1.0f);
        g_cursor[idx] = 0;
    }
    if (idx == 0) g_off[N_NODES] = N_EDGES;
}

__global__ void k_fill(const int* __restrict__ src, const int* __restrict__ dst) {
    int e = blockIdx.x * blockDim.x + threadIdx.x;
    if (e >= N_EDGES) return;
    int d = dst[e];
    int s = src[e];
    int pos = g_off[d] + atomicAdd(&g_cursor[d], 1);
    g_esrc[pos] = s;
    g_ecoef[pos] = g_dinv[s] * g_dinv[d];
}

// ================================================================ GEMM h = in @ W  (64x64 W)
__global__ void k_gemm(const float* __restrict__ in, const float* __restrict__ W,
                       float* __restrict__ out, int relu_in) {
    __shared__ float Ws[64 * 64];
    __shared__ float Xs[64 * 64];
    int tid = threadIdx.x;
    int row0 = blockIdx.x * 64;

#pragma unroll
    for (int i = 0; i < 16; i++) Ws[tid + i * 256] = W[tid + i * 256];

#pragma unroll
    for (int i = 0; i < 16; i++) {
        int lin = tid + i * 256;
        int r = lin >> 6;
        int gr = row0 + r;
        float v = 0.0f;
        if (gr < N_NODES) v = in[gr * 64 + (lin & 63)];
        if (relu_in) v = fmaxf(v, 0.0f);
        Xs[lin] = v;
    }
    __syncthreads();

    int tx = tid & 15;
    int ty = tid >> 4;
    float acc[4][4] = {};

#pragma unroll
    for (int k = 0; k < 64; k += 4) {
        float4 xv[4];
#pragma unroll
        for (int j = 0; j < 4; j++)
            xv[j] = *(const float4*)&Xs[(ty * 4 + j) * 64 + k];
#pragma unroll
        for (int kk = 0; kk < 4; kk++) {
            float w0 = Ws[(k + kk) * 64 + tx];
            float w1 = Ws[(k + kk) * 64 + tx + 16];
            float w2 = Ws[(k + kk) * 64 + tx + 32];
            float w3 = Ws[(k + kk) * 64 + tx + 48];
#pragma unroll
            for (int j = 0; j < 4; j++) {
                float x = (&xv[j].x)[kk];
                acc[j][0] += x * w0;
                acc[j][1] += x * w1;
                acc[j][2] += x * w2;
                acc[j][3] += x * w3;
            }
        }
    }

#pragma unroll
    for (int j = 0; j < 4; j++) {
        int gr = row0 + ty * 4 + j;
        if (gr < N_NODES) {
            out[gr * 64 + tx]      = acc[j][0];
            out[gr * 64 + tx + 16] = acc[j][1];
            out[gr * 64 + tx + 32] = acc[j][2];
            out[gr * 64 + tx + 48] = acc[j][3];
        }
    }
}

// ================================================================ pull aggregation
// 512 threads = 8 nodes/block, 64 threads per node (one per feature).
// acc = h[n]*dinv^2 + b, then += h[src]*coef over CSR edge list. One store, no atomics.
#define AGG_NPB 8
__global__ void k_agg(const float* __restrict__ h, const float* __restrict__ b,
                      float* __restrict__ out) {
    int node = blockIdx.x * AGG_NPB + (threadIdx.x >> 6);
    int f = threadIdx.x & 63;
    if (node >= N_NODES) return;

    float d = g_dinv[node];
    float acc = h[node * 64 + f] * (d * d) + b[f];

    int j = g_off[node];
    int j1 = g_off[node + 1];

    // 4-wide software pipeline for MLP
    for (; j + 4 <= j1; j += 4) {
        int s0 = g_esrc[j];
        int s1 = g_esrc[j + 1];
        int s2 = g_esrc[j + 2];
        int s3 = g_esrc[j + 3];
        float c0 = g_ecoef[j];
        float c1 = g_ecoef[j + 1];
        float c2 = g_ecoef[j + 2];
        float c3 = g_ecoef[j + 3];
        float v0 = h[s0 * 64 + f];
        float v1 = h[s1 * 64 + f];
        float v2 = h[s2 * 64 + f];
        float v3 = h[s3 * 64 + f];
        acc += v0 * c0 + v1 * c1 + v2 * c2 + v3 * c3;
    }
    for (; j < j1; j++) {
        acc += h[g_esrc[j] * 64 + f] * g_ecoef[j];
    }
    out[node * 64 + f] = acc;
}

// ================================================================ pooling + head
__global__ void k_pool_zero() {
    int i = blockIdx.x * blockDim.x + threadIdx.x;
    if (i < N_GRAPHS * FEAT) g_pool[i] = 0.0f;
    if (i < N_GRAPHS) g_cnt[i] = 0.0f;
}

#define POOL_NODES 256
__global__ void k_pool(const float* __restrict__ hin, const int* __restrict__ batch) {
    int f = threadIdx.x;   // 64
    int n0 = blockIdx.x * POOL_NODES;
    if (n0 >= N_NODES) return;
    int n1 = n0 + POOL_NODES;
    if (n1 > N_NODES) n1 = N_NODES;

    float acc = 0.0f;
    float cnt = 0.0f;
    int curg = batch[n0];
    for (int n = n0; n < n1; n++) {
        int g = batch[n];
        if (g != curg) {
            atomicAdd(&g_pool[curg * 64 + f], acc);
            if (f == 0) atomicAdd(&g_cnt[curg], cnt);
            acc = 0.0f;
            cnt = 0.0f;
            curg = g;
        }
        acc += hin[n * 64 + f];
        cnt += 1.0f;
    }
    atomicAdd(&g_pool[curg * 64 + f], acc);
    if (f == 0) atomicAdd(&g_cnt[curg], cnt);
}

__global__ void k_final(const float* __restrict__ Wl, const float* __restrict__ bl,
                        float* __restrict__ out) {
    int g = blockIdx.x;
    int tid = threadIdx.x;  // 64
    __shared__ float p[64];
    float inv = 1.0f / fmaxf(g_cnt[g], 1.0f);
    p[tid] = g_pool[g * 64 + tid] * inv;
    __syncthreads();
    if (tid < N_CLASSES) {
        float acc = bl[tid];
#pragma unroll
        for (int k = 0; k < 64; k++) acc += p[k] * Wl[k * N_CLASSES + tid];
        out[g * N_CLASSES + tid] = acc;
    }
}

// ================================================================ launch
extern "C" void kernel_launch(void* const* d_in, const int* in_sizes, int n_in,
                              void* d_out, int out_size) {
    const float* x     = (const float*)d_in[0];
    const int*   ei    = (const int*)d_in[1];
    const int*   batch = (const int*)d_in[2];
    const float* W1    = (const float*)d_in[3];
    const float* b1    = (const float*)d_in[4];
    const float* W2    = (const float*)d_in[5];
    const float* b2    = (const float*)d_in[6];
    const float* W3    = (const float*)d_in[7];
    const float* b3    = (const float*)d_in[8];
    const float* Wl    = (const float*)d_in[9];
    const float* bl    = (const float*)d_in[10];
    const int* src = ei;
    const int* dst = ei + N_EDGES;

    float *h, *act;
    cudaGetSymbolAddress((void**)&h, g_h);
    cudaGetSymbolAddress((void**)&act, g_act);

    const int TPB = 256;
    int grid_n    = (N_NODES + TPB - 1) / TPB;
    int grid_e    = (N_EDGES + TPB - 1) / TPB;
    int grid_gemm = (N_NODES + 63) / 64;
    int grid_agg  = (N_NODES + AGG_NPB - 1) / AGG_NPB;
    int grid_pool = (N_NODES + POOL_NODES - 1) / POOL_NODES;

    // ---- CSR build (once per launch, reused by all 3 layers) ----
    k_zero_deg<<<grid_n, TPB>>>();
    k_hist<<<grid_e, TPB>>>(dst);
    k_scanA<<<SCAN_NBLK, SCAN_BLK>>>();
    k_scanB<<<1, 32>>>();
    k_scanC<<<grid_n, TPB>>>();
    k_fill<<<grid_e, TPB>>>(src, dst);

    // ---- layer 1 ----
    k_gemm<<<grid_gemm, TPB>>>(x, W1, h, 0);
    k_agg<<<grid_agg, 512>>>(h, b1, act);

    // ---- layer 2 (relu fused into gemm input read) ----
    k_gemm<<<grid_gemm, TPB>>>(act, W2, h, 1);
    k_agg<<<grid_agg, 512>>>(h, b2, act);

    // ---- layer 3 ----
    k_gemm<<<grid_gemm, TPB>>>(act, W3, h, 1);
    k_agg<<<grid_agg, 512>>>(h, b3, act);

    // ---- mean pool + head ----
    k_pool_zero<<<(N_GRAPHS * FEAT + TPB - 1) / TPB, TPB>>>();
    k_pool<<<grid_pool, 64>>>(act, batch);
    k_final<<<N_GRAPHS, 64>>>(Wl, bl, (float*)d_out);
}

// round 3
// speedup vs baseline: 1.5045x; 1.3073x over previous
#include <cuda_runtime.h>
#include <cuda_bf16.h>

#define N_NODES   100000
#define N_EDGES   1600000
#define FEAT      64
#define N_GRAPHS  256
#define N_CLASSES 45

#define SCAN_BLK  1024
#define SCAN_NBLK ((N_NODES + SCAN_BLK - 1) / SCAN_BLK)   // 98

// ---- scratch (static; no allocations allowed) ----
__device__ unsigned g_hb[N_NODES * 32];    // features as packed bf16x2 (32 pairs)
__device__ float g_act0[N_NODES * FEAT];   // GEMM epilogue: h*dinv^2 + b (agg accumulates in place -> act)
__device__ float g_act[N_NODES * FEAT];    // layer output
__device__ float g_dinv[N_NODES];
__device__ int   g_deg[N_NODES];
__device__ int   g_scan[N_NODES];
__device__ int   g_bsum[SCAN_NBLK];
__device__ int   g_off[N_NODES + 1];
__device__ int   g_cursor[N_NODES];
__device__ int2  g_ecsr[N_EDGES];          // (src, coef bits) per CSR slot
__device__ float g_pool[N_GRAPHS * FEAT];
__device__ float g_cnt[N_GRAPHS];

// ================================================================ CSR build
__global__ void k_zero_deg() {
    int i = blockIdx.x * blockDim.x + threadIdx.x;
    if (i < N_NODES) g_deg[i] = 0;
}

__global__ void k_hist(const int* __restrict__ dst) {
    int e = blockIdx.x * blockDim.x + threadIdx.x;
    if (e < N_EDGES) atomicAdd(&g_deg[dst[e]], 1);
}

__global__ void k_scanA() {
    __shared__ int s[SCAN_BLK];
    int t = threadIdx.x;
    int idx = blockIdx.x * SCAN_BLK + t;
    int v = (idx < N_NODES) ? g_deg[idx] : 0;
    s[t] = v;
    __syncthreads();
#pragma unroll
    for (int off = 1; off < SCAN_BLK; off <<= 1) {
        int x = (t >= off) ? s[t - off] : 0;
        __syncthreads();
        s[t] += x;
        __syncthreads();
    }
    if (idx < N_NODES) g_scan[idx] = s[t];
    if (t == SCAN_BLK - 1) g_bsum[blockIdx.x] = s[t];
}

// parallel exclusive scan of the 98 block sums (one block)
__global__ void k_scanB() {
    __shared__ int s[128];
    int t = threadIdx.x;
    int v = (t < SCAN_NBLK) ? g_bsum[t] : 0;
    s[t] = v;
    __syncthreads();
#pragma unroll
    for (int off = 1; off < 128; off <<= 1) {
        int x = (t >= off) ? s[t - off] : 0;
        __syncthreads();
        s[t] += x;
        __syncthreads();
    }
    if (t < SCAN_NBLK) g_bsum[t] = s[t] - v;   // exclusive
}

__global__ void k_scanC() {
    int idx = blockIdx.x * blockDim.x + threadIdx.x;
    if (idx < N_NODES) {
        int deg = g_deg[idx];
        int incl = g_scan[idx] + g_bsum[idx / SCAN_BLK];
        g_off[idx] = incl - deg;
        g_dinv[idx] = rsqrtf((float)deg + 1.0f);
        g_cursor[idx] = 0;
    }
    if (idx == 0) g_off[N_NODES] = N_EDGES;
}

__global__ void k_fill(const int* __restrict__ src, const int* __restrict__ dst) {
    int e = blockIdx.x * blockDim.x + threadIdx.x;
    if (e >= N_EDGES) return;
    int d = dst[e];
    int s = src[e];
    int pos = g_off[d] + atomicAdd(&g_cursor[d], 1);
    float coef = g_dinv[s] * g_dinv[d];
    g_ecsr[pos] = make_int2(s, __float_as_int(coef));
}

// ================================================================ GEMM h = in @ W (64x64), fused epilogue
// Thread computes cols {2tx, 2tx+1, 2tx+32, 2tx+33} of 4 rows.
// Epilogue: g_hb = bf16x2(h), g_act0 = h*dinv^2 + b.
__global__ void k_gemm(const float* __restrict__ in, const float* __restrict__ W,
                       const float* __restrict__ b, int relu_in) {
    __shared__ float Ws[64 * 64];
    __shared__ float Xs[64 * 64];
    int tid = threadIdx.x;
    int row0 = blockIdx.x * 64;

#pragma unroll
    for (int i = 0; i < 16; i++) Ws[tid + i * 256] = W[tid + i * 256];

#pragma unroll
    for (int i = 0; i < 16; i++) {
        int lin = tid + i * 256;
        int r = lin >> 6;
        int gr = row0 + r;
        float v = 0.0f;
        if (gr < N_NODES) v = in[gr * 64 + (lin & 63)];
        if (relu_in) v = fmaxf(v, 0.0f);
        Xs[lin] = v;
    }
    __syncthreads();

    int tx = tid & 15;
    int ty = tid >> 4;
    float acc[4][4] = {};

#pragma unroll
    for (int k = 0; k < 64; k += 4) {
        float4 xv[4];
#pragma unroll
        for (int j = 0; j < 4; j++)
            xv[j] = *(const float4*)&Xs[(ty * 4 + j) * 64 + k];
#pragma unroll
        for (int kk = 0; kk < 4; kk++) {
            float w0 = Ws[(k + kk) * 64 + 2 * tx];
            float w1 = Ws[(k + kk) * 64 + 2 * tx + 1];
            float w2 = Ws[(k + kk) * 64 + 2 * tx + 32];
            float w3 = Ws[(k + kk) * 64 + 2 * tx + 33];
#pragma unroll
            for (int j = 0; j < 4; j++) {
                float x = (&xv[j].x)[kk];
                acc[j][0] += x * w0;
                acc[j][1] += x * w1;
                acc[j][2] += x * w2;
                acc[j][3] += x * w3;
            }
        }
    }

    float b0 = b[2 * tx], b1 = b[2 * tx + 1], b2 = b[2 * tx + 32], b3 = b[2 * tx + 33];

#pragma unroll
    for (int j = 0; j < 4; j++) {
        int gr = row0 + ty * 4 + j;
        if (gr < N_NODES) {
            float d = g_dinv[gr];
            float dd = d * d;
            // bf16 features for gather path
            __nv_bfloat162 p0 = __floats2bfloat162_rn(acc[j][0], acc[j][1]);
            __nv_bfloat162 p1 = __floats2bfloat162_rn(acc[j][2], acc[j][3]);
            g_hb[gr * 32 + tx]      = *(unsigned*)&p0;
            g_hb[gr * 32 + tx + 16] = *(unsigned*)&p1;
            // fp32 self-loop + bias init
            float2 o0 = make_float2(acc[j][0] * dd + b0, acc[j][1] * dd + b1);
            float2 o1 = make_float2(acc[j][2] * dd + b2, acc[j][3] * dd + b3);
            *(float2*)&g_act0[gr * 64 + 2 * tx]      = o0;
            *(float2*)&g_act0[gr * 64 + 2 * tx + 32] = o1;
        }
    }
}

// ================================================================ pull aggregation: warp per node
// lane handles feature pair (2*lane, 2*lane+1). One 128B coalesced load per edge.
__global__ void k_agg(float* __restrict__ out) {
    int node = blockIdx.x * 8 + (threadIdx.x >> 5);
    int lane = threadIdx.x & 31;
    if (node >= N_NODES) return;

    float2 acc = *(const float2*)&g_act0[node * 64 + 2 * lane];

    int j = g_off[node];
    int j1 = g_off[node + 1];

    for (; j + 4 <= j1; j += 4) {
        int2 e0 = __ldg(&g_ecsr[j]);
        int2 e1 = __ldg(&g_ecsr[j + 1]);
        int2 e2 = __ldg(&g_ecsr[j + 2]);
        int2 e3 = __ldg(&g_ecsr[j + 3]);
        unsigned v0 = __ldg(&g_hb[e0.x * 32 + lane]);
        unsigned v1 = __ldg(&g_hb[e1.x * 32 + lane]);
        unsigned v2 = __ldg(&g_hb[e2.x * 32 + lane]);
        unsigned v3 = __ldg(&g_hb[e3.x * 32 + lane]);
        float c0 = __int_as_float(e0.y);
        float c1 = __int_as_float(e1.y);
        float c2 = __int_as_float(e2.y);
        float c3 = __int_as_float(e3.y);
        acc.x += __uint_as_float(v0 << 16) * c0;
        acc.y += __uint_as_float(v0 & 0xffff0000u) * c0;
        acc.x += __uint_as_float(v1 << 16) * c1;
        acc.y += __uint_as_float(v1 & 0xffff0000u) * c1;
        acc.x += __uint_as_float(v2 << 16) * c2;
        acc.y += __uint_as_float(v2 & 0xffff0000u) * c2;
        acc.x += __uint_as_float(v3 << 16) * c3;
        acc.y += __uint_as_float(v3 & 0xffff0000u) * c3;
    }
    for (; j < j1; j++) {
        int2 e = __ldg(&g_ecsr[j]);
        unsigned v = __ldg(&g_hb[e.x * 32 + lane]);
        float c = __int_as_float(e.y);
        acc.x += __uint_as_float(v << 16) * c;
        acc.y += __uint_as_float(v & 0xffff0000u) * c;
    }
    *(float2*)&out[node * 64 + 2 * lane] = acc;
}

// ================================================================ pooling + head
__global__ void k_pool_zero() {
    int i = blockIdx.x * blockDim.x + threadIdx.x;
    if (i < N_GRAPHS * FEAT) g_pool[i] = 0.0f;
    if (i < N_GRAPHS) g_cnt[i] = 0.0f;
}

#define POOL_NODES 256
__global__ void k_pool(const float* __restrict__ hin, const int* __restrict__ batch) {
    int f = threadIdx.x;   // 64
    int n0 = blockIdx.x * POOL_NODES;
    if (n0 >= N_NODES) return;
    int n1 = n0 + POOL_NODES;
    if (n1 > N_NODES) n1 = N_NODES;

    float acc = 0.0f;
    float cnt = 0.0f;
    int curg = batch[n0];
    for (int n = n0; n < n1; n++) {
        int g = batch[n];
        if (g != curg) {
            atomicAdd(&g_pool[curg * 64 + f], acc);
            if (f == 0) atomicAdd(&g_cnt[curg], cnt);
            acc = 0.0f;
            cnt = 0.0f;
            curg = g;
        }
        acc += hin[n * 64 + f];
        cnt += 1.0f;
    }
    atomicAdd(&g_pool[curg * 64 + f], acc);
    if (f == 0) atomicAdd(&g_cnt[curg], cnt);
}

__global__ void k_final(const float* __restrict__ Wl, const float* __restrict__ bl,
                        float* __restrict__ out) {
    int g = blockIdx.x;
    int tid = threadIdx.x;  // 64
    __shared__ float p[64];
    float inv = 1.0f / fmaxf(g_cnt[g], 1.0f);
    p[tid] = g_pool[g * 64 + tid] * inv;
    __syncthreads();
    if (tid < N_CLASSES) {
        float acc = bl[tid];
#pragma unroll
        for (int k = 0; k < 64; k++) acc += p[k] * Wl[k * N_CLASSES + tid];
        out[g * N_CLASSES + tid] = acc;
    }
}

// ================================================================ launch
extern "C" void kernel_launch(void* const* d_in, const int* in_sizes, int n_in,
                              void* d_out, int out_size) {
    const float* x     = (const float*)d_in[0];
    const int*   ei    = (const int*)d_in[1];
    const int*   batch = (const int*)d_in[2];
    const float* W1    = (const float*)d_in[3];
    const float* b1    = (const float*)d_in[4];
    const float* W2    = (const float*)d_in[5];
    const float* b2    = (const float*)d_in[6];
    const float* W3    = (const float*)d_in[7];
    const float* b3    = (const float*)d_in[8];
    const float* Wl    = (const float*)d_in[9];
    const float* bl    = (const float*)d_in[10];
    const int* src = ei;
    const int* dst = ei + N_EDGES;

    float* act;
    cudaGetSymbolAddress((void**)&act, g_act);

    const int TPB = 256;
    int grid_n    = (N_NODES + TPB - 1) / TPB;
    int grid_e    = (N_EDGES + TPB - 1) / TPB;
    int grid_gemm = (N_NODES + 63) / 64;
    int grid_agg  = (N_NODES + 7) / 8;
    int grid_pool = (N_NODES + POOL_NODES - 1) / POOL_NODES;

    // ---- CSR build (once, reused by all 3 layers) ----
    k_zero_deg<<<grid_n, TPB>>>();
    k_hist<<<grid_e, TPB>>>(dst);
    k_scanA<<<SCAN_NBLK, SCAN_BLK>>>();
    k_scanB<<<1, 128>>>();
    k_scanC<<<grid_n, TPB>>>();
    k_fill<<<grid_e, TPB>>>(src, dst);

    // ---- layer 1 ----
    k_gemm<<<grid_gemm, TPB>>>(x, W1, b1, 0);
    k_agg<<<grid_agg, 256>>>(act);

    // ---- layer 2 ----
    k_gemm<<<grid_gemm, TPB>>>(act, W2, b2, 1);
    k_agg<<<grid_agg, 256>>>(act);

    // ---- layer 3 ----
    k_gemm<<<grid_gemm, TPB>>>(act, W3, b3, 1);
    k_agg<<<grid_agg, 256>>>(act);

    // ---- mean pool + head ----
    k_pool_zero<<<(N_GRAPHS * FEAT + TPB - 1) / TPB, TPB>>>();
    k_pool<<<grid_pool, 64>>>(act, batch);
    k_final<<<N_GRAPHS, 64>>>(Wl, bl, (float*)d_out);
}

// round 5
// speedup vs baseline: 1.7267x; 1.1476x over previous
#include <cuda_runtime.h>
#include <cuda_bf16.h>

#define N_NODES   100000
#define N_EDGES   1600000
#define FEAT      64
#define N_GRAPHS  256
#define N_CLASSES 45

#define SCAN_BLK  1024
#define SCAN_NBLK ((N_NODES + SCAN_BLK - 1) / SCAN_BLK)   // 98

// ---- scratch (static; no allocations allowed) ----
__device__ unsigned g_hb[N_NODES * 32];    // bf16x2(h * dinv), 32 pairs per node
__device__ float g_act[N_NODES * FEAT];    // layer output (fp32)
__device__ float g_dinv[N_NODES];
__device__ int   g_deg[N_NODES];
__device__ int   g_scan[N_NODES];
__device__ int   g_bsum[SCAN_NBLK];
__device__ int   g_off[N_NODES + 1];
__device__ int   g_cursor[N_NODES];
__device__ int   g_esrc[N_EDGES];          // CSR: src per slot (only payload needed)
__device__ float g_pool[N_GRAPHS * FEAT];
__device__ float g_cnt[N_GRAPHS];

// ================================================================ CSR build
__global__ void k_zero() {   // deg + pool + cnt in one pass
    int i = blockIdx.x * blockDim.x + threadIdx.x;
    if (i < N_NODES) g_deg[i] = 0;
    if (i < N_GRAPHS * FEAT) g_pool[i] = 0.0f;
    if (i < N_GRAPHS) g_cnt[i] = 0.0f;
}

__global__ void k_hist(const int* __restrict__ dst) {
    int e = blockIdx.x * blockDim.x + threadIdx.x;
    if (e < N_EDGES) atomicAdd(&g_deg[dst[e]], 1);
}

__global__ void k_scanA() {
    __shared__ int s[SCAN_BLK];
    int t = threadIdx.x;
    int idx = blockIdx.x * SCAN_BLK + t;
    int v = (idx < N_NODES) ? g_deg[idx] : 0;
    s[t] = v;
    __syncthreads();
#pragma unroll
    for (int off = 1; off < SCAN_BLK; off <<= 1) {
        int x = (t >= off) ? s[t - off] : 0;
        __syncthreads();
        s[t] += x;
        __syncthreads();
    }
    if (idx < N_NODES) g_scan[idx] = s[t];
    if (t == SCAN_BLK - 1) g_bsum[blockIdx.x] = s[t];
}

// exclusive scan of 98 block sums: shuffle warp scans + cross-warp fixup
__global__ void k_scanB() {
    int t = threadIdx.x;            // 128
    int lane = t & 31;
    int w = t >> 5;
    int orig = (t < SCAN_NBLK) ? g_bsum[t] : 0;
    int v = orig;
#pragma unroll
    for (int o = 1; o < 32; o <<= 1) {
        int x = __shfl_up_sync(0xffffffffu, v, o);
        if (lane >= o) v += x;
    }
    __shared__ int ws[4];
    if (lane == 31) ws[w] = v;
    __syncthreads();
    int add = 0;
#pragma unroll
    for (int k = 0; k < 4; k++)
        if (k < w) add += ws[k];
    if (t < SCAN_NBLK) g_bsum[t] = v + add - orig;   // exclusive
}

__global__ void k_scanC() {
    int idx = blockIdx.x * blockDim.x + threadIdx.x;
    if (idx < N_NODES) {
        int deg = g_deg[idx];
        int incl = g_scan[idx] + g_bsum[idx / SCAN_BLK];
        g_off[idx] = incl - deg;
        g_dinv[idx] = rsqrtf((float)deg + 1.0f);
        g_cursor[idx] = 0;
    }
    if (idx == 0) g_off[N_NODES] = N_EDGES;
}

__global__ void k_fill(const int* __restrict__ src, const int* __restrict__ dst) {
    int e = blockIdx.x * blockDim.x + threadIdx.x;
    if (e >= N_EDGES) return;
    int d = dst[e];
    int pos = g_off[d] + atomicAdd(&g_cursor[d], 1);
    g_esrc[pos] = src[e];
}

// ================================================================ GEMM h = in @ W (64x64)
// Epilogue writes ONLY g_hb = bf16x2(h * dinv).
__global__ void k_gemm(const float* __restrict__ in, const float* __restrict__ W,
                       int relu_in) {
    __shared__ float Ws[64 * 64];
    __shared__ float Xs[64 * 64];
    int tid = threadIdx.x;
    int row0 = blockIdx.x * 64;

#pragma unroll
    for (int i = 0; i < 16; i++) Ws[tid + i * 256] = W[tid + i * 256];

#pragma unroll
    for (int i = 0; i < 16; i++) {
        int lin = tid + i * 256;
        int r = lin >> 6;
        int gr = row0 + r;
        float v = 0.0f;
        if (gr < N_NODES) v = in[gr * 64 + (lin & 63)];
        if (relu_in) v = fmaxf(v, 0.0f);
        Xs[lin] = v;
    }
    __syncthreads();

    int tx = tid & 15;
    int ty = tid >> 4;
    float acc[4][4] = {};

#pragma unroll
    for (int k = 0; k < 64; k += 4) {
        float4 xv[4];
#pragma unroll
        for (int j = 0; j < 4; j++)
            xv[j] = *(const float4*)&Xs[(ty * 4 + j) * 64 + k];
#pragma unroll
        for (int kk = 0; kk < 4; kk++) {
            float w0 = Ws[(k + kk) * 64 + 2 * tx];
            float w1 = Ws[(k + kk) * 64 + 2 * tx + 1];
            float w2 = Ws[(k + kk) * 64 + 2 * tx + 32];
            float w3 = Ws[(k + kk) * 64 + 2 * tx + 33];
#pragma unroll
            for (int j = 0; j < 4; j++) {
                float x = (&xv[j].x)[kk];
                acc[j][0] += x * w0;
                acc[j][1] += x * w1;
                acc[j][2] += x * w2;
                acc[j][3] += x * w3;
            }
        }
    }

#pragma unroll
    for (int j = 0; j < 4; j++) {
        int gr = row0 + ty * 4 + j;
        if (gr < N_NODES) {
            float d = g_dinv[gr];
            __nv_bfloat162 p0 = __floats2bfloat162_rn(acc[j][0] * d, acc[j][1] * d);
            __nv_bfloat162 p1 = __floats2bfloat162_rn(acc[j][2] * d, acc[j][3] * d);
            g_hb[gr * 32 + tx]      = *(unsigned*)&p0;
            g_hb[gr * 32 + tx + 16] = *(unsigned*)&p1;
        }
    }
}

// ================================================================ pull aggregation: warp per node
// acc = hb[node] + sum hb[src];  out = acc * dinv[node] + b
__global__ void k_agg(const float* __restrict__ b, float* __restrict__ out) {
    int node = blockIdx.x * 8 + (threadIdx.x >> 5);
    int lane = threadIdx.x & 31;
    if (node >= N_NODES) return;

    unsigned own = g_hb[node * 32 + lane];
    float2 acc;
    acc.x = __uint_as_float(own << 16);
    acc.y = __uint_as_float(own & 0xffff0000u);

    int j = g_off[node];
    int j1 = g_off[node + 1];

    for (; j + 8 <= j1; j += 8) {
        int s0 = __ldg(&g_esrc[j]);
        int s1 = __ldg(&g_esrc[j + 1]);
        int s2 = __ldg(&g_esrc[j + 2]);
        int s3 = __ldg(&g_esrc[j + 3]);
        int s4 = __ldg(&g_esrc[j + 4]);
        int s5 = __ldg(&g_esrc[j + 5]);
        int s6 = __ldg(&g_esrc[j + 6]);
        int s7 = __ldg(&g_esrc[j + 7]);
        unsigned v0 = __ldg(&g_hb[s0 * 32 + lane]);
        unsigned v1 = __ldg(&g_hb[s1 * 32 + lane]);
        unsigned v2 = __ldg(&g_hb[s2 * 32 + lane]);
        unsigned v3 = __ldg(&g_hb[s3 * 32 + lane]);
        unsigned v4 = __ldg(&g_hb[s4 * 32 + lane]);
        unsigned v5 = __ldg(&g_hb[s5 * 32 + lane]);
        unsigned v6 = __ldg(&g_hb[s6 * 32 + lane]);
        unsigned v7 = __ldg(&g_hb[s7 * 32 + lane]);
        acc.x += __uint_as_float(v0 << 16);
        acc.y += __uint_as_float(v0 & 0xffff0000u);
        acc.x += __uint_as_float(v1 << 16);
        acc.y += __uint_as_float(v1 & 0xffff0000u);
        acc.x += __uint_as_float(v2 << 16);
        acc.y += __uint_as_float(v2 & 0xffff0000u);
        acc.x += __uint_as_float(v3 << 16);
        acc.y += __uint_as_float(v3 & 0xffff0000u);
        acc.x += __uint_as_float(v4 << 16);
        acc.y += __uint_as_float(v4 & 0xffff0000u);
        acc.x += __uint_as_float(v5 << 16);
        acc.y += __uint_as_float(v5 & 0xffff0000u);
        acc.x += __uint_as_float(v6 << 16);
        acc.y += __uint_as_float(v6 & 0xffff0000u);
        acc.x += __uint_as_float(v7 << 16);
        acc.y += __uint_as_float(v7 & 0xffff0000u);
    }
    for (; j < j1; j++) {
        unsigned v = __ldg(&g_hb[__ldg(&g_esrc[j]) * 32 + lane]);
        acc.x += __uint_as_float(v << 16);
        acc.y += __uint_as_float(v & 0xffff0000u);
    }

    float d = g_dinv[node];
    float2 r;
    r.x = acc.x * d + b[2 * lane];
    r.y = acc.y * d + b[2 * lane + 1];
    *(float2*)&out[node * 64 + 2 * lane] = r;
}

// ================================================================ pooling + head
#define POOL_NODES 256
__global__ void k_pool(const float* __restrict__ hin, const int* __restrict__ batch) {
    int f = threadIdx.x;   // 64
    int n0 = blockIdx.x * POOL_NODES;
    if (n0 >= N_NODES) return;
    int n1 = n0 + POOL_NODES;
    if (n1 > N_NODES) n1 = N_NODES;

    float acc = 0.0f;
    float cnt = 0.0f;
    int curg = batch[n0];
    for (int n = n0; n < n1; n++) {
        int g = batch[n];
        if (g != curg) {
            atomicAdd(&g_pool[curg * 64 + f], acc);
            if (f == 0) atomicAdd(&g_cnt[curg], cnt);
            acc = 0.0f;
            cnt = 0.0f;
            curg = g;
        }
        acc += hin[n * 64 + f];
        cnt += 1.0f;
    }
    atomicAdd(&g_pool[curg * 64 + f], acc);
    if (f == 0) atomicAdd(&g_cnt[curg], cnt);
}

__global__ void k_final(const float* __restrict__ Wl, const float* __restrict__ bl,
                        float* __restrict__ out) {
    int g = blockIdx.x;
    int tid = threadIdx.x;  // 64
    __shared__ float p[64];
    float inv = 1.0f / fmaxf(g_cnt[g], 1.0f);
    p[tid] = g_pool[g * 64 + tid] * inv;
    __syncthreads();
    if (tid < N_CLASSES) {
        float acc = bl[tid];
#pragma unroll
        for (int k = 0; k < 64; k++) acc += p[k] * Wl[k * N_CLASSES + tid];
        out[g * N_CLASSES + tid] = acc;
    }
}

// ================================================================ launch
extern "C" void kernel_launch(void* const* d_in, const int* in_sizes, int n_in,
                              void* d_out, int out_size) {
    const float* x     = (const float*)d_in[0];
    const int*   ei    = (const int*)d_in[1];
    const int*   batch = (const int*)d_in[2];
    const float* W1    = (const float*)d_in[3];
    const float* b1    = (const float*)d_in[4];
    const float* W2    = (const float*)d_in[5];
    const float* b2    = (const float*)d_in[6];
    const float* W3    = (const float*)d_in[7];
    const float* b3    = (const float*)d_in[8];
    const float* Wl    = (const float*)d_in[9];
    const float* bl    = (const float*)d_in[10];
    const int* src = ei;
    const int* dst = ei + N_EDGES;

    float* act;
    cudaGetSymbolAddress((void**)&act, g_act);

    const int TPB = 256;
    int grid_n    = (N_NODES + TPB - 1) / TPB;
    int grid_e    = (N_EDGES + TPB - 1) / TPB;
    int grid_gemm = (N_NODES + 63) / 64;
    int grid_agg  = (N_NODES + 7) / 8;
    int grid_pool = (N_NODES + POOL_NODES - 1) / POOL_NODES;

    // ---- CSR build (once, reused by all 3 layers) ----
    k_zero<<<grid_n, TPB>>>();
    k_hist<<<grid_e, TPB>>>(dst);
    k_scanA<<<SCAN_NBLK, SCAN_BLK>>>();
    k_scanB<<<1, 128>>>();
    k_scanC<<<grid_n, TPB>>>();
    k_fill<<<grid_e, TPB>>>(src, dst);

    // ---- layer 1 ----
    k_gemm<<<grid_gemm, TPB>>>(x, W1, 0);
    k_agg<<<grid_agg, 256>>>(b1, act);

    // ---- layer 2 ----
    k_gemm<<<grid_gemm, TPB>>>(act, W2, 1);
    k_agg<<<grid_agg, 256>>>(b2, act);

    // ---- layer 3 ----
    k_gemm<<<grid_gemm, TPB>>>(act, W3, 1);
    k_agg<<<grid_agg, 256>>>(b3, act);

    // ---- mean pool + head ----
    k_pool<<<grid_pool, 64>>>(act, batch);
    k_final<<<N_GRAPHS, 64>>>(Wl, bl, (float*)d_out);
}